// round 1
// baseline (speedup 1.0000x reference)
#include <cuda_runtime.h>

#define NUM_ENT 50000
#define NUM_REL 237
#define REXT    238
#define D       64
#define BN_EPS  1e-5f

// ---------------- device scratch (no allocations allowed) ----------------
__device__ float g_SO[NUM_ENT * D];      // scatter sum, mask=1 edges
__device__ float g_SI[NUM_ENT * D];      // scatter sum, mask=0 edges
__device__ float g_ntmp[NUM_ENT * D];    // pre-BN node output
__device__ float g_nbuf[NUM_ENT * D];    // post-layer-0 node features
__device__ float g_rext[REXT * D];       // [r ; loop_rel]
__device__ float g_rnext[NUM_REL * D];   // layer-0 relation output
__device__ float g_sum[D], g_sumsq[D];   // BN stats accumulators
__device__ float g_scale[D], g_shift[D]; // folded BN affine

// ---------------- zero scatter buffers + stats ----------------
__global__ void zero_kernel() {
    const int n4 = NUM_ENT * D / 4;
    float4 z = make_float4(0.f, 0.f, 0.f, 0.f);
    int stride = gridDim.x * blockDim.x;
    for (int i = blockIdx.x * blockDim.x + threadIdx.x; i < n4; i += stride) {
        reinterpret_cast<float4*>(g_SO)[i] = z;
        reinterpret_cast<float4*>(g_SI)[i] = z;
    }
    int t = blockIdx.x * blockDim.x + threadIdx.x;
    if (t < D) { g_sum[t] = 0.f; g_sumsq[t] = 0.f; }
}

// ---------------- r_ext = concat(r, loop_rel) ----------------
__global__ void build_rext(const float* __restrict__ r_in,
                           const float* __restrict__ loop_rel, int layer) {
    int i = blockIdx.x * blockDim.x + threadIdx.x;
    const float* r = layer ? g_rnext : r_in;
    if (i < NUM_REL * D)      g_rext[i] = r[i];
    else if (i < REXT * D)    g_rext[i] = loop_rel[i - NUM_REL * D];
}

// ---------------- edge scatter: comp_h = n[src]*r_ext[etype]*norm, red into S_O/S_I ----------------
// half-warp (16 lanes) per edge, float4 per lane (64 floats = 256B coalesced)
__global__ __launch_bounds__(256) void edge_scatter(
    const float* __restrict__ nfeat_in0,
    const int*   __restrict__ src,
    const int*   __restrict__ dst,
    const int*   __restrict__ etype,
    const int*   __restrict__ mask,
    const float* __restrict__ norm,
    int E, int layer)
{
    const float* __restrict__ nf = layer ? g_nbuf : nfeat_in0;
    int gid = blockIdx.x * blockDim.x + threadIdx.x;
    int e = gid >> 4;
    if (e >= E) return;
    int c = (gid & 15) * 4;

    int s  = __ldg(src + e);
    int d  = __ldg(dst + e);
    int t  = __ldg(etype + e);
    int m  = __ldg(mask + e);
    float nm = __ldg(norm + e);

    float4 nv = __ldg(reinterpret_cast<const float4*>(nf + s * D + c));
    float4 rv = __ldg(reinterpret_cast<const float4*>(g_rext + t * D + c));

    float4 cm;
    cm.x = nv.x * rv.x * nm;
    cm.y = nv.y * rv.y * nm;
    cm.z = nv.z * rv.z * nm;
    cm.w = nv.w * rv.w * nm;

    float* base = (m ? g_SO : g_SI) + (size_t)d * D + c;
    asm volatile("red.global.add.v4.f32 [%0], {%1,%2,%3,%4};"
                 :: "l"(base), "f"(cm.x), "f"(cm.y), "f"(cm.z), "f"(cm.w)
                 : "memory");
}

// ---------------- node transform: fused 3-way GEMM + BN stats ----------------
// out = (n .* lr) @ W_S^T + S_O @ W_O^T + S_I @ W_I^T, all * 1/3
// W's transposed (and lr, 1/3 folded) into SMEM. Warp per row; lane owns 2 output cols.
__global__ __launch_bounds__(256) void node_transform(
    const float* __restrict__ nfeat_in0,
    const float* __restrict__ WS, const float* __restrict__ WO,
    const float* __restrict__ WI, const float* __restrict__ LR,
    int rows, int layer)
{
    __shared__ float sWS[D * D];
    __shared__ float sWO[D * D];
    __shared__ float sWI[D * D];
    const float third = 1.0f / 3.0f;
    for (int i = threadIdx.x; i < D * D; i += 256) {
        int j = i >> 6, k = i & 63;
        sWS[k * D + j] = __ldg(WS + i) * __ldg(LR + k) * third;
        sWO[k * D + j] = __ldg(WO + i) * third;
        sWI[k * D + j] = __ldg(WI + i) * third;
    }
    __syncthreads();

    const float* __restrict__ nf = layer ? g_nbuf : nfeat_in0;
    int lane = threadIdx.x & 31;
    int warp = (blockIdx.x * 256 + threadIdx.x) >> 5;
    int nwarps = (gridDim.x * 256) >> 5;
    int j0 = lane * 2;

    float s0 = 0.f, s1 = 0.f, q0 = 0.f, q1 = 0.f;

    for (int row = warp; row < rows; row += nwarps) {
        const float* xn = nf   + (size_t)row * D;
        const float* xo = g_SO + (size_t)row * D;
        const float* xi = g_SI + (size_t)row * D;
        float a0 = 0.f, a1 = 0.f;

#define NT_STEP(K, VN, VO, VI) {                                   \
        float2 ws = *reinterpret_cast<const float2*>(sWS + (K) * D + j0); \
        float2 wo = *reinterpret_cast<const float2*>(sWO + (K) * D + j0); \
        float2 wi = *reinterpret_cast<const float2*>(sWI + (K) * D + j0); \
        a0 += (VN) * ws.x + (VO) * wo.x + (VI) * wi.x;             \
        a1 += (VN) * ws.y + (VO) * wo.y + (VI) * wi.y; }

#pragma unroll 4
        for (int kk = 0; kk < D; kk += 4) {
            float4 vn = __ldg(reinterpret_cast<const float4*>(xn + kk));
            float4 vo = __ldg(reinterpret_cast<const float4*>(xo + kk));
            float4 vi = __ldg(reinterpret_cast<const float4*>(xi + kk));
            NT_STEP(kk + 0, vn.x, vo.x, vi.x)
            NT_STEP(kk + 1, vn.y, vo.y, vi.y)
            NT_STEP(kk + 2, vn.z, vo.z, vi.z)
            NT_STEP(kk + 3, vn.w, vo.w, vi.w)
        }
#undef NT_STEP

        g_ntmp[(size_t)row * D + j0]     = a0;
        g_ntmp[(size_t)row * D + j0 + 1] = a1;
        s0 += a0; s1 += a1;
        q0 += a0 * a0; q1 += a1 * a1;
    }

    atomicAdd(&g_sum[j0],       s0);
    atomicAdd(&g_sum[j0 + 1],   s1);
    atomicAdd(&g_sumsq[j0],     q0);
    atomicAdd(&g_sumsq[j0 + 1], q1);
}

// ---------------- BN finalize: fold mean/var/gamma/beta into scale+shift ----------------
__global__ void bn_finalize(const float* __restrict__ gamma,
                            const float* __restrict__ beta, int N) {
    int j = threadIdx.x;
    if (j >= D) return;
    float invN = 1.0f / (float)N;
    float mean = g_sum[j] * invN;
    float var  = fmaxf(g_sumsq[j] * invN - mean * mean, 0.f);
    float rstd = rsqrtf(var + BN_EPS);
    float g = __ldg(gamma + j);
    g_scale[j] = rstd * g;
    g_shift[j] = __ldg(beta + j) - mean * rstd * g;
}

// ---------------- BN apply + tanh ----------------
__global__ __launch_bounds__(256) void bn_apply(float* __restrict__ out_n, int n4, int layer) {
    int i = blockIdx.x * blockDim.x + threadIdx.x;
    if (i >= n4) return;
    float* dst = layer ? out_n : g_nbuf;
    int col = (i & 15) * 4;
    float4 x  = reinterpret_cast<const float4*>(g_ntmp)[i];
    float4 sc = *reinterpret_cast<const float4*>(g_scale + col);
    float4 sh = *reinterpret_cast<const float4*>(g_shift + col);
    float4 y;
    y.x = tanhf(x.x * sc.x + sh.x);
    y.y = tanhf(x.y * sc.y + sh.y);
    y.z = tanhf(x.z * sc.z + sh.z);
    y.w = tanhf(x.w * sc.w + sh.w);
    reinterpret_cast<float4*>(dst)[i] = y;
}

// ---------------- relation update: r_next = (r_ext @ W_R^T)[:-1] ----------------
__global__ __launch_bounds__(256) void rel_update(const float* __restrict__ WR,
                                                  float* __restrict__ out_r, int layer) {
    int g = blockIdx.x * blockDim.x + threadIdx.x;
    int t = g >> 5;
    if (t >= NUM_REL) return;
    int lane = g & 31;
    int j0 = lane * 2;
    float* dst = layer ? out_r : g_rnext;
    float a0 = 0.f, a1 = 0.f;
#pragma unroll 8
    for (int k = 0; k < D; k++) {
        float v = g_rext[t * D + k];
        a0 += v * __ldg(WR + j0 * D + k);
        a1 += v * __ldg(WR + (j0 + 1) * D + k);
    }
    dst[t * D + j0]     = a0;
    dst[t * D + j0 + 1] = a1;
}

// ---------------- launch ----------------
extern "C" void kernel_launch(void* const* d_in, const int* in_sizes, int n_in,
                              void* d_out, int out_size) {
    const float* n0   = (const float*)d_in[0];
    const float* r0   = (const float*)d_in[1];
    const float* norm = (const float*)d_in[2];
    const int*   src  = (const int*)d_in[3];
    const int*   dst  = (const int*)d_in[4];
    const int*   et   = (const int*)d_in[5];
    const int*   msk  = (const int*)d_in[6];
    const int E    = in_sizes[3];
    const int rows = in_sizes[0] / D;

    float* out   = (float*)d_out;
    float* out_n = out;
    float* out_r = out + (size_t)NUM_ENT * D;

    const int n4 = NUM_ENT * D / 4;

    for (int l = 0; l < 2; l++) {
        const float* WO = (const float*)d_in[7  + 7 * l];
        const float* WI = (const float*)d_in[8  + 7 * l];
        const float* WS = (const float*)d_in[9  + 7 * l];
        const float* WR = (const float*)d_in[10 + 7 * l];
        const float* LR = (const float*)d_in[11 + 7 * l];
        const float* GA = (const float*)d_in[12 + 7 * l];
        const float* BE = (const float*)d_in[13 + 7 * l];

        zero_kernel<<<512, 256>>>();
        build_rext<<<(REXT * D + 255) / 256, 256>>>(r0, LR, l);
        {
            long long threads = (long long)E * 16;
            int blocks = (int)((threads + 255) / 256);
            edge_scatter<<<blocks, 256>>>(n0, src, dst, et, msk, norm, E, l);
        }
        node_transform<<<592, 256>>>(n0, WS, WO, WI, LR, rows, l);
        bn_finalize<<<1, 64>>>(GA, BE, rows);
        bn_apply<<<(n4 + 255) / 256, 256>>>(out_n, n4, l);
        rel_update<<<(NUM_REL * 32 + 255) / 256, 256>>>(WR, out_r, l);
    }
}